// round 16
// baseline (speedup 1.0000x reference)
#include <cuda_runtime.h>
#include <cstdint>

// ---------------------------------------------------------------------------
// SCAConv via 3xTF32 mma.sync GEMMs (R15).
// Per lm (=l&31): D[row=(h,lhp,b)x1024, col 0..71] = A[row,144] x B[144,col],
//   B cols = [32 G-j | t(b2) | 32 conv-o].
// K1 (grid 128 = lm x hq): builds B-frags in smem (no prep kernel), warp =
//   (h-pair, k-half) so each B frag load feeds 6 MMAs. Partials per k-half
//   go to scratch. K2 sums halves + bias + H*G epilogue.
// ---------------------------------------------------------------------------

typedef unsigned long long ull;

__device__ float g_D[2*32*1024*72];   // [kh][lm][row][col] partial D

__device__ __forceinline__ uint32_t f2tf32(float f) {
    uint32_t u; asm("cvt.rna.tf32.f32 %0, %1;" : "=r"(u) : "f"(f)); return u;
}

#define MMA(d, a0,a1,a2,a3, b0,b1) \
    asm volatile("mma.sync.aligned.m16n8k8.row.col.f32.tf32.tf32.f32 " \
        "{%0,%1,%2,%3},{%4,%5,%6,%7},{%8,%9},{%0,%1,%2,%3};" \
        : "+f"(d[0]),"+f"(d[1]),"+f"(d[2]),"+f"(d[3]) \
        : "r"(a0),"r"(a1),"r"(a2),"r"(a3),"r"(b0),"r"(b1))

// ---------------- K1 ----------------
#define PAT_N 13824                     // float2 (hi,lo) entries
#define BS_N  (18*9*32)                 // 5184 uint4
#define K1_SMEM (PAT_N*8 + BS_N*16)     // 193536 B

__global__ __launch_bounds__(512, 1)
void k1_kernel(const float* __restrict__ x, const float* __restrict__ kern,
               const float* __restrict__ W2, const float* __restrict__ b2) {
    extern __shared__ char smp[];
    float2* pat = (float2*)smp;
    uint4*  Bs  = (uint4*)(smp + PAT_N*8);

    const int tid = threadIdx.x;
    const int lm  = blockIdx.x >> 2;
    const int hq  = blockIdx.x & 3;

    // ---- build B frags in smem: [ks 18][nt 9][lane 32] = {hi0,hi1,lo0,lo1} ----
    for (int i = tid; i < BS_N; i += 512) {
        int lane = i & 31;
        int r = i >> 5;
        int nt = r % 9, ks = r / 9;
        int kq = lane & 3, n = lane >> 2;
        int k0 = ks*8 + kq, k1 = k0 + 4;
        float w0, w1;
        if (nt < 4)       { w0 = W2[(lm*144+k0)*32 + nt*8 + n]; w1 = W2[(lm*144+k1)*32 + nt*8 + n]; }
        else if (nt == 4) { w0 = (n==0) ? b2[lm*144+k0] : 0.f;  w1 = (n==0) ? b2[lm*144+k1] : 0.f; }
        else              { int o = (nt-5)*8 + n; w0 = kern[o*144+k0]; w1 = kern[o*144+k1]; }
        uint32_t h0 = f2tf32(w0), h1 = f2tf32(w1);
        uint32_t l0 = f2tf32(w0 - __uint_as_float(h0));
        uint32_t l1 = f2tf32(w1 - __uint_as_float(h1));
        Bs[i] = make_uint4(h0, h1, l0, l1);
    }

    // ---- stage x patch hi/lo: pat[((c*18+gr)*6+lhp*3+kc)*8+b] ----
    for (int i = tid; i < PAT_N; i += 512) {
        int kc  = i % 3;  int t2 = i / 3;
        int lhp = t2 & 1; t2 >>= 1;
        int b   = t2 & 7; t2 >>= 3;
        int gr  = t2 % 18;
        int c   = t2 / 18;
        int row = hq*16 - 1 + gr;
        int col = lhp*32 + lm - 1 + kc;
        float v = 0.f;
        if (row >= 0 && row < 64 && col >= 0 && col < 64)
            v = x[((b*16 + c)*64 + row)*64 + col];
        uint32_t hv = f2tf32(v);
        float lv = v - __uint_as_float(hv);
        pat[((c*18 + gr)*6 + lhp*3 + kc)*8 + b] =
            make_float2(__uint_as_float(hv), lv);
    }
    __syncthreads();

    // ---- mainloop: warp = (h-pair hp, k-half kh) ----
    const int wid  = tid >> 5;
    const int lane = tid & 31;
    const int kq   = lane & 3;
    const int bq   = lane >> 2;
    const int hp   = wid >> 1;          // 0..7
    const int kh   = wid & 1;           // 0/1
    const int hl0  = hp*2;              // local h rows base

    float d[2][9][4];
    #pragma unroll
    for (int hh = 0; hh < 2; hh++)
        #pragma unroll
        for (int nt = 0; nt < 9; nt++)
            #pragma unroll
            for (int q = 0; q < 4; q++) d[hh][nt][q] = 0.f;

    for (int ks = kh*9; ks < kh*9 + 9; ++ks) {
        int k0 = ks*8 + kq, k1 = k0 + 4;
        int c0 = k0/9, q0 = k0 - 9*c0, kr0 = q0/3, kc0 = q0 - 3*kr0;
        int c1 = k1/9, q1 = k1 - 9*c1, kr1 = q1/3, kc1 = q1 - 3*kr1;

        // A frags for both h's (hi/lo packed in float2)
        uint32_t ah[2][4], al[2][4];
        #pragma unroll
        for (int hh = 0; hh < 2; hh++) {
            int o0 = ((c0*18 + hl0 + hh + kr0)*6 + kc0)*8 + bq;
            int o1 = ((c1*18 + hl0 + hh + kr1)*6 + kc1)*8 + bq;
            float2 A0 = pat[o0], A1 = pat[o0 + 24];
            float2 A2 = pat[o1], A3 = pat[o1 + 24];
            ah[hh][0] = __float_as_uint(A0.x); al[hh][0] = __float_as_uint(A0.y);
            ah[hh][1] = __float_as_uint(A1.x); al[hh][1] = __float_as_uint(A1.y);
            ah[hh][2] = __float_as_uint(A2.x); al[hh][2] = __float_as_uint(A2.y);
            ah[hh][3] = __float_as_uint(A3.x); al[hh][3] = __float_as_uint(A3.y);
        }

        const uint4* bp = Bs + ks*(9*32) + lane;
        #pragma unroll
        for (int nt = 0; nt < 9; ++nt) {
            uint4 B = bp[nt*32];
            #pragma unroll
            for (int hh = 0; hh < 2; hh++) {
                MMA(d[hh][nt], ah[hh][0],ah[hh][1],ah[hh][2],ah[hh][3], B.x, B.y); // hi*hi
                MMA(d[hh][nt], ah[hh][0],ah[hh][1],ah[hh][2],ah[hh][3], B.z, B.w); // hi*lo
                MMA(d[hh][nt], al[hh][0],al[hh][1],al[hh][2],al[hh][3], B.x, B.y); // lo*hi
            }
        }
    }

    // ---- store partials ----
    #pragma unroll
    for (int hh = 0; hh < 2; hh++) {
        int h = hq*16 + hl0 + hh;
        float* base = g_D + ((ull)(kh*32 + lm)*1024 + h*16 + bq)*72;
        #pragma unroll
        for (int nt = 0; nt < 9; nt++) {
            int col = nt*8 + 2*kq;
            *(float2*)(base + col)        = make_float2(d[hh][nt][0], d[hh][nt][1]);
            *(float2*)(base + 8*72 + col) = make_float2(d[hh][nt][2], d[hh][nt][3]);
        }
    }
}

// ---------------- K2: epilogue ----------------
#define GS_STR 76
#define K2_SMEM ((8*32*GS_STR + 1024 + 32)*4)

__global__ __launch_bounds__(512, 1)
void k2_kernel(const float* __restrict__ bias, const float* __restrict__ cpar,
               const float* __restrict__ W1, const float* __restrict__ b1,
               float* __restrict__ out) {
    extern __shared__ float sm2[];
    float* Gst = sm2;                       // [b][lm][76]: 32 G | t | pad | 32 conv @40
    float* Hs  = sm2 + 8*32*GS_STR;
    float* bss = Hs + 1024;

    const int tid = threadIdx.x;
    const int lhb = blockIdx.x;
    const int h = lhb >> 1, lhp = lhb & 1;

    for (int i = tid; i < 8*32*72; i += 512) {
        int c = i % 72; int t2 = i / 72;
        int lmi = t2 & 31; int b = t2 >> 5;
        ull ro = ((ull)lmi*1024 + h*16 + lhp*8 + b)*72 + c;
        float v = g_D[ro] + g_D[(ull)32*1024*72 + ro];
        int cc = (c < 40) ? c : c;          // G at 0..31, t at 32, conv at 40..71
        Gst[(b*32 + lmi)*GS_STR + cc] = v;
    }
    for (int i = tid; i < 1024; i += 512) {
        int o = i >> 5, j = i & 31;
        int p = o*128 + lhb;
        float inp[12];
        inp[0] = (float)(p >> 6) * (1.f/64.f);
        inp[1] = 1.f - inp[0];
        inp[2] = (float)(p & 63) * (1.f/64.f);
        inp[3] = 1.f - inp[2];
        #pragma unroll
        for (int k = 0; k < 8; k++) inp[4+k] = cpar[k];
        float s = b1[j];
        #pragma unroll
        for (int k = 0; k < 12; k++) s += W1[j*12 + k] * inp[k];
        Hs[i] = fmaxf(s, 0.f);
    }
    if (tid < 32) bss[tid] = bias[tid];
    __syncthreads();

    const int b   = tid >> 6;
    const int oh  = (tid >> 5) & 1;
    const int lmi = tid & 31;
    const float* gb = Gst + (b*32 + lmi)*GS_STR;

    float g[32];
    #pragma unroll
    for (int q = 0; q < 8; q++) {
        float4 v = *(const float4*)(gb + q*4);
        g[q*4+0] = v.x; g[q*4+1] = v.y; g[q*4+2] = v.z; g[q*4+3] = v.w;
    }
    float tv = gb[32];

    float* ob = out + ((b*32 + oh*16)*64 + h)*64 + lhp*32 + lmi;
    #pragma unroll
    for (int oo = 0; oo < 16; oo++) {
        int o = oh*16 + oo;
        float s = bss[o] + tv + gb[40 + o];
        const float4* h4 = (const float4*)(Hs + o*32);
        #pragma unroll
        for (int q = 0; q < 8; q++) {
            float4 hv = h4[q];
            s += hv.x*g[q*4] + hv.y*g[q*4+1] + hv.z*g[q*4+2] + hv.w*g[q*4+3];
        }
        ob[oo*4096] = s;
    }
}

extern "C" void kernel_launch(void* const* d_in, const int* in_sizes, int n_in,
                              void* d_out, int out_size)
{
    const float* x    = (const float*)d_in[0];   // (8,16,64,64)
    const float* kern = (const float*)d_in[1];   // (32,144)
    const float* bias = (const float*)d_in[2];   // (32,)
    const float* cpar = (const float*)d_in[3];   // (1,8)
    const float* W1   = (const float*)d_in[4];   // (32,12)
    const float* b1   = (const float*)d_in[5];   // (32,)
    const float* W2   = (const float*)d_in[6];   // (4608,32)
    const float* b2   = (const float*)d_in[7];   // (4608,)
    float* out = (float*)d_out;                  // (8,32,64,64)

    cudaFuncSetAttribute(k1_kernel, cudaFuncAttributeMaxDynamicSharedMemorySize, K1_SMEM);
    cudaFuncSetAttribute(k2_kernel, cudaFuncAttributeMaxDynamicSharedMemorySize, K2_SMEM);

    k1_kernel<<<128, 512, K1_SMEM>>>(x, kern, W2, b2);
    k2_kernel<<<128, 512, K2_SMEM>>>(bias, cpar, W1, b1, out);
}